// round 5
// baseline (speedup 1.0000x reference)
#include <cuda_runtime.h>
#include <stdint.h>
#include <math.h>

#define NE 8
#define HID 2048
#define INTER 1408
#define TOT 8192
#define MAXTILES 96
#define MAXGRIDY 72
#define RSTR 80

// ---------------------------------------------------------------------------
// Device globals
// ---------------------------------------------------------------------------
__device__ int g_tile_expert[MAXTILES];
__device__ int g_tile_row0[MAXTILES];
__device__ int g_tile_nrows[MAXTILES];
__device__ int g_ntiles;

__device__ int8_t g_xq1[(size_t)TOT * HID];
__device__ int8_t g_xq0[(size_t)TOT * HID];
__device__ float  g_xs[TOT];

// transposed quantized weights: [E][N][K], K contiguous, two int8 planes
__device__ int8_t g_gq1[(size_t)NE * INTER * HID];
__device__ int8_t g_gq0[(size_t)NE * INTER * HID];
__device__ int8_t g_uq1[(size_t)NE * INTER * HID];
__device__ int8_t g_uq0[(size_t)NE * INTER * HID];
__device__ int8_t g_dq1[(size_t)NE * HID * INTER];
__device__ int8_t g_dq0[(size_t)NE * HID * INTER];
__device__ float g_sg[NE * INTER], g_ig[NE * INTER];
__device__ float g_su[NE * INTER], g_iu[NE * INTER];
__device__ float g_sd[NE * HID],  g_id[NE * HID];

__device__ float  g_hf[(size_t)TOT * INTER];
__device__ int8_t g_hq1[(size_t)TOT * INTER];
__device__ int8_t g_hq0[(size_t)TOT * INTER];
__device__ float  g_hs[TOT];

__device__ float g_pm[(size_t)3 * 8 * NE * 2048];

// ---------------------------------------------------------------------------
// PTX helpers (base-target: cp.async sm_80, ldmatrix sm_75, imma sm_80)
// ---------------------------------------------------------------------------
__device__ __forceinline__ uint32_t smem_u32(const void* p) {
    uint32_t a;
    asm("{ .reg .u64 t; cvta.to.shared.u64 t, %1; cvt.u32.u64 %0, t; }"
        : "=r"(a) : "l"(p));
    return a;
}
__device__ __forceinline__ void cp16(uint32_t dst, const void* src, int srcsize) {
    asm volatile("cp.async.cg.shared.global [%0], [%1], 16, %2;"
                 :: "r"(dst), "l"(src), "r"(srcsize));
}
#define CP_COMMIT() asm volatile("cp.async.commit_group;")
#define CP_WAIT1()  asm volatile("cp.async.wait_group 1;")

__device__ __forceinline__ void imma(int& c0, int& c1, int& c2, int& c3,
                                     const uint32_t a[4], const uint32_t* b) {
    asm volatile(
        "mma.sync.aligned.m16n8k32.row.col.s32.s8.s8.s32 "
        "{%0,%1,%2,%3},{%4,%5,%6,%7},{%8,%9},{%0,%1,%2,%3};"
        : "+r"(c0), "+r"(c1), "+r"(c2), "+r"(c3)
        : "r"(a[0]), "r"(a[1]), "r"(a[2]), "r"(a[3]), "r"(b[0]), "r"(b[1]));
}
#define IMMA(C, A, B) imma((C)[0], (C)[1], (C)[2], (C)[3], (A), (B))

__device__ __forceinline__ void ldm_x4(uint32_t r[4], uint32_t addr) {
    asm volatile("ldmatrix.sync.aligned.m8n8.x4.shared.b16 {%0,%1,%2,%3}, [%4];"
                 : "=r"(r[0]), "=r"(r[1]), "=r"(r[2]), "=r"(r[3]) : "r"(addr));
}
// A fragment m16 x k32 (int8, k0 in BYTES): a0..a3 in IMMA order
__device__ __forceinline__ void fragA(uint32_t a[4], uint32_t tile, int rb, int k0, int lane) {
    uint32_t addr = tile + (uint32_t)(rb + (lane & 15)) * RSTR
                         + (uint32_t)(k0 + (lane >> 4) * 16);
    ldm_x4(a, addr);
}
// B fragment pair: 16 n-rows x k32 -> (b[0],b[1]) = n-octet 0, (b[2],b[3]) = n-octet 1
__device__ __forceinline__ void fragB2(uint32_t b[4], uint32_t tile, int nb, int k0, int lane) {
    uint32_t addr = tile + (uint32_t)(nb + ((lane >> 4) * 8) + (lane & 7)) * RSTR
                         + (uint32_t)(k0 + ((lane >> 3) & 1) * 16);
    ldm_x4(b, addr);
}

// int8 tiles: rows x 64 bytes, row stride 80 B (conflict-free)
__device__ __forceinline__ void load_t128(uint32_t sdst, const int8_t* src,
                                          int ldk, int k0, int nvalid, int tid) {
#pragma unroll
    for (int i = 0; i < 2; i++) {
        int id = tid + i * 256;
        int r = id >> 2, c = id & 3;
        cp16(sdst + r * RSTR + c * 16, src + (size_t)r * ldk + k0 + c * 16,
             r < nvalid ? 16 : 0);
    }
}
__device__ __forceinline__ void load_t64(uint32_t sdst, const int8_t* src,
                                         int ldk, int k0, int tid) {
    int r = tid >> 2, c = tid & 3;
    cp16(sdst + r * RSTR + c * 16, src + (size_t)r * ldk + k0 + c * 16, 16);
}

// quantize v -> 256*h + l, clamped to +-32512
__device__ __forceinline__ void qsplit(float v, float iv, int& h, int& l) {
    int q = __float2int_rn(v * iv);
    q = q > 32512 ? 32512 : (q < -32512 ? -32512 : q);
    h = (q + 128) >> 8;
    l = q - (h << 8);
}

__device__ __forceinline__ float blockmax(float v) {
    __shared__ float red[8];
#pragma unroll
    for (int o = 16; o; o >>= 1) v = fmaxf(v, __shfl_xor_sync(0xffffffffu, v, o));
    if ((threadIdx.x & 31) == 0) red[threadIdx.x >> 5] = v;
    __syncthreads();
    v = red[threadIdx.x & 7];
#pragma unroll
    for (int o = 4; o; o >>= 1) v = fmaxf(v, __shfl_xor_sync(0xffffffffu, v, o));
    return v;
}

// ---------------------------------------------------------------------------
// Setup + quantization kernels
// ---------------------------------------------------------------------------
__global__ void setup_tiles(const int* __restrict__ tpe) {
    int off = 0, nt = 0;
    for (int e = 0; e < NE; e++) {
        int n = tpe[e];
        for (int r = 0; r < n; r += 128) {
            g_tile_expert[nt] = e;
            g_tile_row0[nt]   = off + r;
            g_tile_nrows[nt]  = (n - r < 128) ? (n - r) : 128;
            nt++;
        }
        off += n;
    }
    g_ntiles = nt;
}

__global__ void quant_x(const float* __restrict__ x) {
    const int row = blockIdx.x, tid = threadIdx.x;
    const float4* p = (const float4*)(x + (size_t)row * HID);
    float4 v0 = p[tid], v1 = p[tid + 256];
    float m = fmaxf(fmaxf(fmaxf(fabsf(v0.x), fabsf(v0.y)), fmaxf(fabsf(v0.z), fabsf(v0.w))),
                    fmaxf(fmaxf(fabsf(v1.x), fabsf(v1.y)), fmaxf(fabsf(v1.z), fabsf(v1.w))));
    m = blockmax(m);
    if (tid == 0) g_xs[row] = m * (1.f / 32512.f);
    const float iv = (m > 0.f) ? (32512.f / m) : 0.f;
    uchar4* o1 = (uchar4*)(g_xq1 + (size_t)row * HID);
    uchar4* o0 = (uchar4*)(g_xq0 + (size_t)row * HID);
#pragma unroll
    for (int i = 0; i < 2; i++) {
        float4 v = i ? v1 : v0;
        int h0, l0, h1, l1, h2, l2, h3, l3;
        qsplit(v.x, iv, h0, l0); qsplit(v.y, iv, h1, l1);
        qsplit(v.z, iv, h2, l2); qsplit(v.w, iv, h3, l3);
        o1[tid + i * 256] = make_uchar4((uint8_t)h0, (uint8_t)h1, (uint8_t)h2, (uint8_t)h3);
        o0[tid + i * 256] = make_uchar4((uint8_t)l0, (uint8_t)l1, (uint8_t)l2, (uint8_t)l3);
    }
}

__global__ void quant_h() {
    const int row = blockIdx.x, tid = threadIdx.x;
    const float4* p = (const float4*)(g_hf + (size_t)row * INTER);
    const int NG = INTER / 4;  // 352
    float4 v0 = p[tid];
    float4 v1 = (tid < NG - 256) ? p[tid + 256] : make_float4(0.f, 0.f, 0.f, 0.f);
    float m = fmaxf(fmaxf(fmaxf(fabsf(v0.x), fabsf(v0.y)), fmaxf(fabsf(v0.z), fabsf(v0.w))),
                    fmaxf(fmaxf(fabsf(v1.x), fabsf(v1.y)), fmaxf(fabsf(v1.z), fabsf(v1.w))));
    m = blockmax(m);
    if (tid == 0) g_hs[row] = m * (1.f / 32512.f);
    const float iv = (m > 0.f) ? (32512.f / m) : 0.f;
    uchar4* o1 = (uchar4*)(g_hq1 + (size_t)row * INTER);
    uchar4* o0 = (uchar4*)(g_hq0 + (size_t)row * INTER);
    {
        int h0, l0, h1, l1, h2, l2, h3, l3;
        qsplit(v0.x, iv, h0, l0); qsplit(v0.y, iv, h1, l1);
        qsplit(v0.z, iv, h2, l2); qsplit(v0.w, iv, h3, l3);
        o1[tid] = make_uchar4((uint8_t)h0, (uint8_t)h1, (uint8_t)h2, (uint8_t)h3);
        o0[tid] = make_uchar4((uint8_t)l0, (uint8_t)l1, (uint8_t)l2, (uint8_t)l3);
    }
    if (tid < NG - 256) {
        int h0, l0, h1, l1, h2, l2, h3, l3;
        qsplit(v1.x, iv, h0, l0); qsplit(v1.y, iv, h1, l1);
        qsplit(v1.z, iv, h2, l2); qsplit(v1.w, iv, h3, l3);
        o1[tid + 256] = make_uchar4((uint8_t)h0, (uint8_t)h1, (uint8_t)h2, (uint8_t)h3);
        o0[tid + 256] = make_uchar4((uint8_t)l0, (uint8_t)l1, (uint8_t)l2, (uint8_t)l3);
    }
}

// per-column abs-max of [E][K][N], partial over K/8 chunk
__global__ void colmax_part(const float* __restrict__ w, float* __restrict__ pm,
                            int K, int N) {
    const int e = blockIdx.y, z = blockIdx.z;
    const int n = blockIdx.x * 128 + threadIdx.x;
    const int kc = K / 8;
    const float* p = w + (size_t)e * K * N + (size_t)z * kc * N + n;
    float m = 0.f;
#pragma unroll 4
    for (int k = 0; k < kc; k++) m = fmaxf(m, fabsf(p[(size_t)k * N]));
    pm[((size_t)z * NE + e) * 2048 + n] = m;
}
__global__ void colmax_fin(const float* __restrict__ pm, float* __restrict__ s,
                           float* __restrict__ iv, int N) {
    const int e = blockIdx.y;
    const int n = blockIdx.x * 128 + threadIdx.x;
    float m = 0.f;
#pragma unroll
    for (int z = 0; z < 8; z++) m = fmaxf(m, pm[((size_t)z * NE + e) * 2048 + n]);
    s[e * N + n]  = m * (1.f / 32512.f);
    iv[e * N + n] = (m > 0.f) ? (32512.f / m) : 0.f;
}

// [E][K][N] fp32 -> [E][N][K] int8 planes, per-n scale
__global__ void transpose_quant(const float* __restrict__ in,
                                int8_t* __restrict__ o1, int8_t* __restrict__ o0,
                                const float* __restrict__ iv, int K, int N) {
    __shared__ float t[32][33];
    const int e = blockIdx.z;
    const float* src = in + (size_t)e * K * N;
    const int k0 = blockIdx.x * 32, n0 = blockIdx.y * 32;
    const int tx = threadIdx.x, ty = threadIdx.y;
#pragma unroll
    for (int j = 0; j < 32; j += 8)
        t[ty + j][tx] = src[(size_t)(k0 + ty + j) * N + n0 + tx];
    __syncthreads();
#pragma unroll
    for (int j = 0; j < 32; j += 8) {
        const int n = n0 + ty + j;
        const float ivv = iv[e * N + n];
        int h, l;
        qsplit(t[tx][ty + j], ivv, h, l);
        const size_t o = ((size_t)e * N + n) * K + k0 + tx;
        o1[o] = (int8_t)h;
        o0[o] = (int8_t)l;
    }
}

// ---------------------------------------------------------------------------
// Fused gate+up grouped GEMM (int8 two-plane). CTA: M=128 x N=64 per matrix,
// BK=64 bytes. 8 warps (4M x 2N), warp 32x32 per matrix. 3-stage pipeline.
// Stage (40960 B): Aq1 0, Aq0 10240, Gq1 20480, Gq0 25600, Uq1 30720, Uq0 35840
// ---------------------------------------------------------------------------
#define GU_BUF 40960
#define GU_SMEM (3 * GU_BUF)

__global__ void __launch_bounds__(256) k_gateup() {
    const int t = blockIdx.y;
    if (t >= g_ntiles) return;
    const int e     = g_tile_expert[t];
    const int row0  = g_tile_row0[t];
    const int nrows = g_tile_nrows[t];
    const int n0    = blockIdx.x * 64;

    extern __shared__ char smem[];
    const uint32_t sb = smem_u32(smem);
    const int tid  = threadIdx.x;
    const int lane = tid & 31;
    const int wid  = tid >> 5;
    const int wm   = wid & 3;
    const int wn   = wid >> 2;

    const int8_t* x1 = g_xq1 + (size_t)row0 * HID;
    const int8_t* x0 = g_xq0 + (size_t)row0 * HID;
    const size_t wb = (size_t)e * INTER * HID + (size_t)n0 * HID;
    const int8_t* gq1 = g_gq1 + wb;
    const int8_t* gq0 = g_gq0 + wb;
    const int8_t* uq1 = g_uq1 + wb;
    const int8_t* uq0 = g_uq0 + wb;

    int cg1[2][4][4], cg2[2][4][4], cu1[2][4][4], cu2[2][4][4];
#pragma unroll
    for (int i = 0; i < 2; i++)
#pragma unroll
        for (int j = 0; j < 4; j++)
#pragma unroll
            for (int k = 0; k < 4; k++) {
                cg1[i][j][k] = 0; cg2[i][j][k] = 0;
                cu1[i][j][k] = 0; cu2[i][j][k] = 0;
            }

#define GU_LOAD(s, k0)                                          \
    do {                                                        \
        uint32_t o = sb + (s) * GU_BUF;                         \
        load_t128(o,         x1,  HID, (k0), nrows, tid);       \
        load_t128(o + 10240, x0,  HID, (k0), nrows, tid);       \
        load_t64(o + 20480,  gq1, HID, (k0), tid);              \
        load_t64(o + 25600,  gq0, HID, (k0), tid);              \
        load_t64(o + 30720,  uq1, HID, (k0), tid);              \
        load_t64(o + 35840,  uq0, HID, (k0), tid);              \
        CP_COMMIT();                                            \
    } while (0)

    GU_LOAD(0, 0);
    GU_LOAD(1, 64);

    const int KT = HID / 64;
    for (int kt = 0; kt < KT; kt++) {
        CP_WAIT1();
        __syncthreads();
        if (kt + 2 < KT) GU_LOAD((kt + 2) % 3, (kt + 2) * 64);
        else             CP_COMMIT();

        const uint32_t buf = sb + (kt % 3) * GU_BUF;
#pragma unroll
        for (int ks = 0; ks < 2; ks++) {
            const int k0 = ks * 32;
            uint32_t A1[2][4], A0[2][4];
            fragA(A1[0], buf,         wm * 32,      k0, lane);
            fragA(A1[1], buf,         wm * 32 + 16, k0, lane);
            fragA(A0[0], buf + 10240, wm * 32,      k0, lane);
            fragA(A0[1], buf + 10240, wm * 32 + 16, k0, lane);
#pragma unroll
            for (int p = 0; p < 2; p++) {
                const int nb = wn * 32 + p * 16;
                uint32_t G1[4], G0[4], U1[4], U0[4];
                fragB2(G1, buf + 20480, nb, k0, lane);
                fragB2(G0, buf + 25600, nb, k0, lane);
                fragB2(U1, buf + 30720, nb, k0, lane);
                fragB2(U0, buf + 35840, nb, k0, lane);
#pragma unroll
                for (int mt = 0; mt < 2; mt++)
#pragma unroll
                    for (int no = 0; no < 2; no++) {
                        const int q = p * 2 + no;
                        IMMA(cg1[mt][q], A1[mt], G1 + no * 2);
                        IMMA(cg2[mt][q], A1[mt], G0 + no * 2);
                        IMMA(cg2[mt][q], A0[mt], G1 + no * 2);
                        IMMA(cu1[mt][q], A1[mt], U1 + no * 2);
                        IMMA(cu2[mt][q], A1[mt], U0 + no * 2);
                        IMMA(cu2[mt][q], A0[mt], U1 + no * 2);
                    }
            }
        }
    }

    // epilogue: dequant, silu(gate)*up -> g_hf (fp32)
#pragma unroll
    for (int mt = 0; mt < 2; mt++)
#pragma unroll
        for (int half = 0; half < 2; half++) {
            const int r = wm * 32 + mt * 16 + half * 8 + (lane >> 2);
            if (r < nrows) {
                const float sx = g_xs[row0 + r];
                float* hp = g_hf + (size_t)(row0 + r) * INTER + n0 + wn * 32;
#pragma unroll
                for (int q = 0; q < 4; q++) {
                    const int ncol = (q >> 1) * 16 + (q & 1) * 8 + (lane & 3) * 2;
                    const int gn = e * INTER + n0 + wn * 32 + ncol;
                    const float f0 = 65536.f * (float)cg1[mt][q][half * 2]
                                   + 256.f   * (float)cg2[mt][q][half * 2];
                    const float f1 = 65536.f * (float)cg1[mt][q][half * 2 + 1]
                                   + 256.f   * (float)cg2[mt][q][half * 2 + 1];
                    const float e0 = 65536.f * (float)cu1[mt][q][half * 2]
                                   + 256.f   * (float)cu2[mt][q][half * 2];
                    const float e1 = 65536.f * (float)cu1[mt][q][half * 2 + 1]
                                   + 256.f   * (float)cu2[mt][q][half * 2 + 1];
                    const float gg0 = sx * g_sg[gn]     * f0;
                    const float gg1 = sx * g_sg[gn + 1] * f1;
                    const float uu0 = sx * g_su[gn]     * e0;
                    const float uu1 = sx * g_su[gn + 1] * e1;
                    float2 h;
                    h.x = uu0 * gg0 / (1.f + __expf(-gg0));
                    h.y = uu1 * gg1 / (1.f + __expf(-gg1));
                    *(float2*)(hp + ncol) = h;
                }
            }
        }
}

// ---------------------------------------------------------------------------
// Down grouped GEMM (int8 two-plane). CTA: M=128 x N=64, BK=64.
// Stage (30720 B): Aq1 0, Aq0 10240, Bq1 20480, Bq0 25600
// ---------------------------------------------------------------------------
#define DN_BUF 30720
#define DN_SMEM (3 * DN_BUF)

__global__ void __launch_bounds__(256) k_down(const float* __restrict__ probs,
                                              float* __restrict__ out) {
    const int t = blockIdx.y;
    if (t >= g_ntiles) return;
    const int e     = g_tile_expert[t];
    const int row0  = g_tile_row0[t];
    const int nrows = g_tile_nrows[t];
    const int n0    = blockIdx.x * 64;

    extern __shared__ char smem[];
    const uint32_t sb = smem_u32(smem);
    const int tid  = threadIdx.x;
    const int lane = tid & 31;
    const int wid  = tid >> 5;
    const int wm   = wid & 3;
    const int wn   = wid >> 2;

    const int8_t* a1 = g_hq1 + (size_t)row0 * INTER;
    const int8_t* a0 = g_hq0 + (size_t)row0 * INTER;
    const size_t wb = (size_t)e * HID * INTER + (size_t)n0 * INTER;
    const int8_t* b1 = g_dq1 + wb;
    const int8_t* b0 = g_dq0 + wb;

    int cc1[2][4][4], cc2[2][4][4];
#pragma unroll
    for (int i = 0; i < 2; i++)
#pragma unroll
        for (int j = 0; j < 4; j++)
#pragma unroll
            for (int k = 0; k < 4; k++) { cc1[i][j][k] = 0; cc2[i][j][k] = 0; }

#define DN_LOAD(s, k0)                                          \
    do {                                                        \
        uint32_t o = sb + (s) * DN_BUF;                         \
        load_t128(o,         a1, INTER, (k0), nrows, tid);      \
        load_t128(o + 10240, a0, INTER, (k0), nrows, tid);      \
        load_t64(o + 20480,  b1, INTER, (k0), tid);             \
        load_t64(o + 25600,  b0, INTER, (k0), tid);             \
        CP_COMMIT();                                            \
    } while (0)

    DN_LOAD(0, 0);
    DN_LOAD(1, 64);

    const int KT = INTER / 64;
    for (int kt = 0; kt < KT; kt++) {
        CP_WAIT1();
        __syncthreads();
        if (kt + 2 < KT) DN_LOAD((kt + 2) % 3, (kt + 2) * 64);
        else             CP_COMMIT();

        const uint32_t buf = sb + (kt % 3) * DN_BUF;
#pragma unroll
        for (int ks = 0; ks < 2; ks++) {
            const int k0 = ks * 32;
            uint32_t A1[2][4], A0[2][4];
            fragA(A1[0], buf,         wm * 32,      k0, lane);
            fragA(A1[1], buf,         wm * 32 + 16, k0, lane);
            fragA(A0[0], buf + 10240, wm * 32,      k0, lane);
            fragA(A0[1], buf + 10240, wm * 32 + 16, k0, lane);
#pragma unroll
            for (int p = 0; p < 2; p++) {
                const int nb = wn * 32 + p * 16;
                uint32_t B1[4], B0[4];
                fragB2(B1, buf + 20480, nb, k0, lane);
                fragB2(B0, buf + 25600, nb, k0, lane);
#pragma unroll
                for (int mt = 0; mt < 2; mt++)
#pragma unroll
                    for (int no = 0; no < 2; no++) {
                        const int q = p * 2 + no;
                        IMMA(cc1[mt][q], A1[mt], B1 + no * 2);
                        IMMA(cc2[mt][q], A1[mt], B0 + no * 2);
                        IMMA(cc2[mt][q], A0[mt], B1 + no * 2);
                    }
            }
        }
    }

    // epilogue: dequant, scale by probs, write fp32
#pragma unroll
    for (int mt = 0; mt < 2; mt++)
#pragma unroll
        for (int half = 0; half < 2; half++) {
            const int r = wm * 32 + mt * 16 + half * 8 + (lane >> 2);
            if (r < nrows) {
                const float ps = probs[row0 + r] * g_hs[row0 + r];
                float* op = out + (size_t)(row0 + r) * HID + n0 + wn * 32;
#pragma unroll
                for (int q = 0; q < 4; q++) {
                    const int ncol = (q >> 1) * 16 + (q & 1) * 8 + (lane & 3) * 2;
                    const int dn = e * HID + n0 + wn * 32 + ncol;
                    const float f0 = 65536.f * (float)cc1[mt][q][half * 2]
                                   + 256.f   * (float)cc2[mt][q][half * 2];
                    const float f1 = 65536.f * (float)cc1[mt][q][half * 2 + 1]
                                   + 256.f   * (float)cc2[mt][q][half * 2 + 1];
                    float2 v;
                    v.x = ps * g_sd[dn]     * f0;
                    v.y = ps * g_sd[dn + 1] * f1;
                    *(float2*)(op + ncol) = v;
                }
            }
        }
}

// ---------------------------------------------------------------------------
// Launch
// ---------------------------------------------------------------------------
extern "C" void kernel_launch(void* const* d_in, const int* in_sizes, int n_in,
                              void* d_out, int out_size) {
    const float* x     = (const float*)d_in[0];
    const float* probs = (const float*)d_in[1];
    const float* wg    = (const float*)d_in[2];
    const float* wu    = (const float*)d_in[3];
    const float* wd    = (const float*)d_in[4];
    const int*   tpe   = (const int*)d_in[5];
    float*       out   = (float*)d_out;

    cudaFuncSetAttribute(k_gateup, cudaFuncAttributeMaxDynamicSharedMemorySize, GU_SMEM);
    cudaFuncSetAttribute(k_down,   cudaFuncAttributeMaxDynamicSharedMemorySize, DN_SMEM);

    float *pm, *sg, *ig, *su, *iu, *sd, *id;
    int8_t *gq1, *gq0, *uq1, *uq0, *dq1, *dq0;
    cudaGetSymbolAddress((void**)&pm,  g_pm);
    cudaGetSymbolAddress((void**)&sg,  g_sg);
    cudaGetSymbolAddress((void**)&ig,  g_ig);
    cudaGetSymbolAddress((void**)&su,  g_su);
    cudaGetSymbolAddress((void**)&iu,  g_iu);
    cudaGetSymbolAddress((void**)&sd,  g_sd);
    cudaGetSymbolAddress((void**)&id,  g_id);
    cudaGetSymbolAddress((void**)&gq1, g_gq1);
    cudaGetSymbolAddress((void**)&gq0, g_gq0);
    cudaGetSymbolAddress((void**)&uq1, g_uq1);
    cudaGetSymbolAddress((void**)&uq0, g_uq0);
    cudaGetSymbolAddress((void**)&dq1, g_dq1);
    cudaGetSymbolAddress((void**)&dq0, g_dq0);
    float* pm_g = pm;
    float* pm_u = pm + (size_t)8 * NE * 2048;
    float* pm_d = pm + (size_t)16 * NE * 2048;

    setup_tiles<<<1, 1>>>(tpe);
    quant_x<<<TOT, 256>>>(x);

    colmax_part<<<dim3(INTER / 128, NE, 8), 128>>>(wg, pm_g, HID, INTER);
    colmax_part<<<dim3(INTER / 128, NE, 8), 128>>>(wu, pm_u, HID, INTER);
    colmax_part<<<dim3(HID / 128,  NE, 8), 128>>>(wd, pm_d, INTER, HID);
    colmax_fin<<<dim3(INTER / 128, NE), 128>>>(pm_g, sg, ig, INTER);
    colmax_fin<<<dim3(INTER / 128, NE), 128>>>(pm_u, su, iu, INTER);
    colmax_fin<<<dim3(HID / 128,  NE), 128>>>(pm_d, sd, id, HID);

    dim3 tb(32, 8);
    transpose_quant<<<dim3(HID / 32, INTER / 32, NE), tb>>>(wg, gq1, gq0, ig, HID, INTER);
    transpose_quant<<<dim3(HID / 32, INTER / 32, NE), tb>>>(wu, uq1, uq0, iu, HID, INTER);
    transpose_quant<<<dim3(INTER / 32, HID / 32, NE), tb>>>(wd, dq1, dq0, id, INTER, HID);

    k_gateup<<<dim3(INTER / 64, MAXGRIDY), 256, GU_SMEM>>>();
    quant_h<<<TOT, 256>>>();
    k_down<<<dim3(HID / 64, MAXGRIDY), 256, DN_SMEM>>>(probs, out);
}

// round 6
// speedup vs baseline: 2.6732x; 2.6732x over previous
#include <cuda_runtime.h>
#include <cuda_bf16.h>
#include <stdint.h>
#include <math.h>

#define NE 8
#define HID 2048
#define INTER 1408
#define TOT 8192
#define MAXTILES 96
#define MAXGRIDY 72

// ---------------------------------------------------------------------------
// Device globals
// ---------------------------------------------------------------------------
__device__ int g_tile_expert[MAXTILES];
__device__ int g_tile_row0[MAXTILES];
__device__ int g_tile_nrows[MAXTILES];
__device__ int g_ntiles;

__device__ __nv_bfloat16 g_xh[(size_t)TOT * HID];
__device__ __nv_bfloat16 g_xl[(size_t)TOT * HID];
// transposed weights: [E][N][K], K contiguous
__device__ __nv_bfloat16 g_wgh[(size_t)NE * INTER * HID];
__device__ __nv_bfloat16 g_wgl[(size_t)NE * INTER * HID];
__device__ __nv_bfloat16 g_wuh[(size_t)NE * INTER * HID];
__device__ __nv_bfloat16 g_wul[(size_t)NE * INTER * HID];
__device__ __nv_bfloat16 g_wdh[(size_t)NE * HID * INTER];
__device__ __nv_bfloat16 g_wdl[(size_t)NE * HID * INTER];
__device__ __nv_bfloat16 g_hh[(size_t)TOT * INTER];
__device__ __nv_bfloat16 g_hl[(size_t)TOT * INTER];

// ---------------------------------------------------------------------------
// Helpers (base-target PTX: mma.sync sm_80, cp.async sm_80, ldmatrix sm_75)
// ---------------------------------------------------------------------------
__device__ __forceinline__ uint32_t smem_u32(const void* p) {
    uint32_t a;
    asm("{ .reg .u64 t; cvta.to.shared.u64 t, %1; cvt.u32.u64 %0, t; }"
        : "=r"(a) : "l"(p));
    return a;
}

__device__ __forceinline__ void cp16(uint32_t dst, const void* src, int srcsize) {
    asm volatile("cp.async.cg.shared.global [%0], [%1], 16, %2;"
                 :: "r"(dst), "l"(src), "r"(srcsize));
}
#define CP_COMMIT() asm volatile("cp.async.commit_group;")
#define CP_WAIT1()  asm volatile("cp.async.wait_group 1;")
#define CP_WAIT0()  asm volatile("cp.async.wait_group 0;")

__device__ __forceinline__ void mma16816(float& c0, float& c1, float& c2, float& c3,
                                         const uint32_t a[4], const uint32_t* b) {
    asm volatile(
        "mma.sync.aligned.m16n8k16.row.col.f32.bf16.bf16.f32 "
        "{%0,%1,%2,%3},{%4,%5,%6,%7},{%8,%9},{%0,%1,%2,%3};"
        : "+f"(c0), "+f"(c1), "+f"(c2), "+f"(c3)
        : "r"(a[0]), "r"(a[1]), "r"(a[2]), "r"(a[3]), "r"(b[0]), "r"(b[1]));
}
#define MMA(C, A, B) mma16816((C)[0], (C)[1], (C)[2], (C)[3], A, B)

__device__ __forceinline__ void ldm_x4(uint32_t r[4], uint32_t addr) {
    asm volatile("ldmatrix.sync.aligned.m8n8.x4.shared.b16 {%0,%1,%2,%3}, [%4];"
                 : "=r"(r[0]), "=r"(r[1]), "=r"(r[2]), "=r"(r[3]) : "r"(addr));
}

// Row stride 80 B (conflict-free for cp.async stores and ldmatrix reads)
#define RSTR 80

// A fragment group (16 rows x 16 k): one ldmatrix.x4 -> mma operand order
__device__ __forceinline__ void fragA(uint32_t a[4], uint32_t tile, int rb, int k0, int lane) {
    uint32_t addr = tile + (uint32_t)(rb + (lane & 15)) * RSTR
                         + (uint32_t)(k0 + (lane >> 4) * 8) * 2;
    ldm_x4(a, addr);
}
// B fragment pair (two adjacent n-octets x 16 k from [n][k] tile)
__device__ __forceinline__ void fragB2(uint32_t b[4], uint32_t tile, int nb, int k0, int lane) {
    uint32_t addr = tile + (uint32_t)(nb + ((lane >> 4) * 8) + (lane & 7)) * RSTR
                         + (uint32_t)(k0 + ((lane >> 3) & 1) * 8) * 2;
    ldm_x4(b, addr);
}

// load 128-row x 32-col bf16 tile via cp.async (zero-fill invalid rows)
__device__ __forceinline__ void load_tile128(uint32_t sdst, const __nv_bfloat16* src,
                                             int ldk, int k0, int nvalid, int tid) {
#pragma unroll
    for (int i = 0; i < 2; i++) {
        int id = tid + i * 256;
        int r = id >> 2, c = id & 3;
        cp16(sdst + r * RSTR + c * 16, src + (size_t)r * ldk + k0 + c * 8,
             r < nvalid ? 16 : 0);
    }
}
__device__ __forceinline__ void load_tile64(uint32_t sdst, const __nv_bfloat16* src,
                                            int ldk, int k0, int tid) {
    int r = tid >> 2, c = tid & 3;
    cp16(sdst + r * RSTR + c * 16, src + (size_t)r * ldk + k0 + c * 8, 16);
}

// ---------------------------------------------------------------------------
// Setup + conversion kernels
// ---------------------------------------------------------------------------
__global__ void setup_tiles(const int* __restrict__ tpe) {
    int off = 0, nt = 0;
    for (int e = 0; e < NE; e++) {
        int n = tpe[e];
        for (int r = 0; r < n; r += 128) {
            g_tile_expert[nt] = e;
            g_tile_row0[nt]   = off + r;
            g_tile_nrows[nt]  = (n - r < 128) ? (n - r) : 128;
            nt++;
        }
        off += n;
    }
    g_ntiles = nt;
}

__global__ void convert_x(const float* __restrict__ x) {
    const size_t n4 = (size_t)TOT * HID / 4;
    for (size_t i = blockIdx.x * blockDim.x + threadIdx.x; i < n4;
         i += (size_t)gridDim.x * blockDim.x) {
        float4 v = ((const float4*)x)[i];
        __nv_bfloat16 h0 = __float2bfloat16(v.x), h1 = __float2bfloat16(v.y);
        __nv_bfloat16 h2 = __float2bfloat16(v.z), h3 = __float2bfloat16(v.w);
        __nv_bfloat16 l0 = __float2bfloat16(v.x - __bfloat162float(h0));
        __nv_bfloat16 l1 = __float2bfloat16(v.y - __bfloat162float(h1));
        __nv_bfloat16 l2 = __float2bfloat16(v.z - __bfloat162float(h2));
        __nv_bfloat16 l3 = __float2bfloat16(v.w - __bfloat162float(h3));
        uint32_t ph0 = (uint32_t)__bfloat16_as_ushort(h0) | ((uint32_t)__bfloat16_as_ushort(h1) << 16);
        uint32_t ph1 = (uint32_t)__bfloat16_as_ushort(h2) | ((uint32_t)__bfloat16_as_ushort(h3) << 16);
        uint32_t pl0 = (uint32_t)__bfloat16_as_ushort(l0) | ((uint32_t)__bfloat16_as_ushort(l1) << 16);
        uint32_t pl1 = (uint32_t)__bfloat16_as_ushort(l2) | ((uint32_t)__bfloat16_as_ushort(l3) << 16);
        ((uint2*)g_xh)[i] = make_uint2(ph0, ph1);
        ((uint2*)g_xl)[i] = make_uint2(pl0, pl1);
    }
}

// z < NE: wg -> g_wgh/g_wgl ; z >= NE: wu -> g_wuh/g_wul   ([E][K][N] -> [E][N][K])
__global__ void transpose_cvt_gu(const float* __restrict__ wg,
                                 const float* __restrict__ wu) {
    __shared__ float t[32][33];
    const int z = blockIdx.z;
    const int e = z & (NE - 1);
    const bool isu = z >= NE;
    const float* src = (isu ? wu : wg) + (size_t)e * HID * INTER;
    __nv_bfloat16* dh = (isu ? g_wuh : g_wgh) + (size_t)e * HID * INTER;
    __nv_bfloat16* dl = (isu ? g_wul : g_wgl) + (size_t)e * HID * INTER;
    const int k0 = blockIdx.x * 32, n0 = blockIdx.y * 32;
    const int tx = threadIdx.x, ty = threadIdx.y;
#pragma unroll
    for (int j = 0; j < 32; j += 8)
        t[ty + j][tx] = src[(size_t)(k0 + ty + j) * INTER + n0 + tx];
    __syncthreads();
#pragma unroll
    for (int j = 0; j < 32; j += 8) {
        float v = t[tx][ty + j];
        __nv_bfloat16 h = __float2bfloat16(v);
        size_t o = (size_t)(n0 + ty + j) * HID + k0 + tx;
        dh[o] = h;
        dl[o] = __float2bfloat16(v - __bfloat162float(h));
    }
}

__global__ void transpose_cvt_d(const float* __restrict__ wd) {
    __shared__ float t[32][33];
    const int e = blockIdx.z;
    const float* src = wd + (size_t)e * INTER * HID;
    __nv_bfloat16* dh = g_wdh + (size_t)e * INTER * HID;
    __nv_bfloat16* dl = g_wdl + (size_t)e * INTER * HID;
    const int k0 = blockIdx.x * 32, n0 = blockIdx.y * 32;
    const int tx = threadIdx.x, ty = threadIdx.y;
#pragma unroll
    for (int j = 0; j < 32; j += 8)
        t[ty + j][tx] = src[(size_t)(k0 + ty + j) * HID + n0 + tx];
    __syncthreads();
#pragma unroll
    for (int j = 0; j < 32; j += 8) {
        float v = t[tx][ty + j];
        __nv_bfloat16 h = __float2bfloat16(v);
        size_t o = (size_t)(n0 + ty + j) * INTER + k0 + tx;
        dh[o] = h;
        dl[o] = __float2bfloat16(v - __bfloat162float(h));
    }
}

// ---------------------------------------------------------------------------
// Fused gate+up grouped GEMM. CTA: M=128 x N=64 (per matrix), BK=32.
// 8 warps (4 M x 2 N), warp = 32x32 per matrix. 2-stage cp.async pipeline.
// Stage layout (40960 B): Ah 0, Al 10240, Bgh 20480, Bgl 25600, Buh 30720, Bul 35840
// ---------------------------------------------------------------------------
#define GU_BUF 40960
#define GU_SMEM (2 * GU_BUF)

__global__ void __launch_bounds__(256, 2) k_gateup() {
    const int t = blockIdx.y;
    if (t >= g_ntiles) return;
    const int e     = g_tile_expert[t];
    const int row0  = g_tile_row0[t];
    const int nrows = g_tile_nrows[t];
    const int n0    = blockIdx.x * 64;

    extern __shared__ char smem[];
    const uint32_t sb = smem_u32(smem);
    const int tid  = threadIdx.x;
    const int lane = tid & 31;
    const int wid  = tid >> 5;
    const int wm   = wid & 3;
    const int wn   = wid >> 2;

    const __nv_bfloat16* xh = g_xh + (size_t)row0 * HID;
    const __nv_bfloat16* xl = g_xl + (size_t)row0 * HID;
    const size_t wbase = (size_t)e * INTER * HID + (size_t)n0 * HID;
    const __nv_bfloat16* gh = g_wgh + wbase;
    const __nv_bfloat16* gl = g_wgl + wbase;
    const __nv_bfloat16* uh = g_wuh + wbase;
    const __nv_bfloat16* ul = g_wul + wbase;

    float cg[2][4][4], cu[2][4][4];
#pragma unroll
    for (int i = 0; i < 2; i++)
#pragma unroll
        for (int j = 0; j < 4; j++)
#pragma unroll
            for (int k = 0; k < 4; k++) { cg[i][j][k] = 0.f; cu[i][j][k] = 0.f; }

#define GU_LOAD(b, k0)                                              \
    do {                                                            \
        uint32_t o = sb + (b) * GU_BUF;                             \
        load_tile128(o,          xh, HID, (k0), nrows, tid);        \
        load_tile128(o + 10240,  xl, HID, (k0), nrows, tid);        \
        load_tile64(o + 20480,   gh, HID, (k0), tid);               \
        load_tile64(o + 25600,   gl, HID, (k0), tid);               \
        load_tile64(o + 30720,   uh, HID, (k0), tid);               \
        load_tile64(o + 35840,   ul, HID, (k0), tid);               \
        CP_COMMIT();                                                \
    } while (0)

    GU_LOAD(0, 0);
    const int KT = HID / 32;
    for (int kt = 0; kt < KT; kt++) {
        const bool more = (kt + 1 < KT);
        if (more) GU_LOAD((kt + 1) & 1, (kt + 1) * 32);
        if (more) CP_WAIT1(); else CP_WAIT0();
        __syncthreads();
        const uint32_t buf = sb + (kt & 1) * GU_BUF;
#pragma unroll
        for (int ks = 0; ks < 2; ks++) {
            const int k0 = ks * 16;
            uint32_t Ah0[4], Ah1[4], Al0[4], Al1[4];
            fragA(Ah0, buf,         wm * 32,      k0, lane);
            fragA(Ah1, buf,         wm * 32 + 16, k0, lane);
            fragA(Al0, buf + 10240, wm * 32,      k0, lane);
            fragA(Al1, buf + 10240, wm * 32 + 16, k0, lane);
#pragma unroll
            for (int p = 0; p < 2; p++) {
                const int nb = wn * 32 + p * 16;
                uint32_t Bgh[4], Bgl[4], Buh[4], Bul[4];
                fragB2(Bgh, buf + 20480, nb, k0, lane);
                fragB2(Bgl, buf + 25600, nb, k0, lane);
                fragB2(Buh, buf + 30720, nb, k0, lane);
                fragB2(Bul, buf + 35840, nb, k0, lane);
                const int q = p * 2;
                MMA(cg[0][q],   Ah0, Bgh);     MMA(cg[0][q],   Ah0, Bgl);     MMA(cg[0][q],   Al0, Bgh);
                MMA(cg[1][q],   Ah1, Bgh);     MMA(cg[1][q],   Ah1, Bgl);     MMA(cg[1][q],   Al1, Bgh);
                MMA(cg[0][q+1], Ah0, Bgh + 2); MMA(cg[0][q+1], Ah0, Bgl + 2); MMA(cg[0][q+1], Al0, Bgh + 2);
                MMA(cg[1][q+1], Ah1, Bgh + 2); MMA(cg[1][q+1], Ah1, Bgl + 2); MMA(cg[1][q+1], Al1, Bgh + 2);
                MMA(cu[0][q],   Ah0, Buh);     MMA(cu[0][q],   Ah0, Bul);     MMA(cu[0][q],   Al0, Buh);
                MMA(cu[1][q],   Ah1, Buh);     MMA(cu[1][q],   Ah1, Bul);     MMA(cu[1][q],   Al1, Buh);
                MMA(cu[0][q+1], Ah0, Buh + 2); MMA(cu[0][q+1], Ah0, Bul + 2); MMA(cu[0][q+1], Al0, Buh + 2);
                MMA(cu[1][q+1], Ah1, Buh + 2); MMA(cu[1][q+1], Ah1, Bul + 2); MMA(cu[1][q+1], Al1, Buh + 2);
            }
        }
        __syncthreads();
    }

    // epilogue: silu(gate)*up -> h hi/lo
#pragma unroll
    for (int mt = 0; mt < 2; mt++)
#pragma unroll
        for (int half = 0; half < 2; half++) {
            const int r = wm * 32 + mt * 16 + half * 8 + (lane >> 2);
            if (r < nrows) {
                __nv_bfloat16* hhp = g_hh + (size_t)(row0 + r) * INTER + n0 + wn * 32;
                __nv_bfloat16* hlp = g_hl + (size_t)(row0 + r) * INTER + n0 + wn * 32;
#pragma unroll
                for (int nt = 0; nt < 4; nt++) {
                    const float gg0 = cg[mt][nt][half * 2], gg1 = cg[mt][nt][half * 2 + 1];
                    const float uu0 = cu[mt][nt][half * 2], uu1 = cu[mt][nt][half * 2 + 1];
                    const float h0 = uu0 * gg0 / (1.f + __expf(-gg0));
                    const float h1 = uu1 * gg1 / (1.f + __expf(-gg1));
                    const __nv_bfloat16 hh0 = __float2bfloat16(h0);
                    const __nv_bfloat16 hh1 = __float2bfloat16(h1);
                    const __nv_bfloat16 ll0 = __float2bfloat16(h0 - __bfloat162float(hh0));
                    const __nv_bfloat16 ll1 = __float2bfloat16(h1 - __bfloat162float(hh1));
                    const int col = nt * 8 + (lane & 3) * 2;
                    *(uint32_t*)(hhp + col) =
                        (uint32_t)__bfloat16_as_ushort(hh0) | ((uint32_t)__bfloat16_as_ushort(hh1) << 16);
                    *(uint32_t*)(hlp + col) =
                        (uint32_t)__bfloat16_as_ushort(ll0) | ((uint32_t)__bfloat16_as_ushort(ll1) << 16);
                }
            }
        }
}

// ---------------------------------------------------------------------------
// Down grouped GEMM. CTA: M=128 x N=128, BK=32, 8 warps (4 x 2), warp 32x64.
// Stage layout (40960 B): Ah 0, Al 10240, Bh 20480, Bl 30720
// ---------------------------------------------------------------------------
#define DN_BUF 40960
#define DN_SMEM (2 * DN_BUF)

__global__ void __launch_bounds__(256, 2) k_down(const float* __restrict__ probs,
                                                 float* __restrict__ out) {
    const int t = blockIdx.y;
    if (t >= g_ntiles) return;
    const int e     = g_tile_expert[t];
    const int row0  = g_tile_row0[t];
    const int nrows = g_tile_nrows[t];
    const int n0    = blockIdx.x * 128;

    extern __shared__ char smem[];
    const uint32_t sb = smem_u32(smem);
    const int tid  = threadIdx.x;
    const int lane = tid & 31;
    const int wid  = tid >> 5;
    const int wm   = wid & 3;
    const int wn   = wid >> 2;

    const __nv_bfloat16* ah = g_hh + (size_t)row0 * INTER;
    const __nv_bfloat16* al = g_hl + (size_t)row0 * INTER;
    const size_t wbase = (size_t)e * HID * INTER + (size_t)n0 * INTER;
    const __nv_bfloat16* bh  = g_wdh + wbase;
    const __nv_bfloat16* blo = g_wdl + wbase;

    float cc[2][8][4];
#pragma unroll
    for (int i = 0; i < 2; i++)
#pragma unroll
        for (int j = 0; j < 8; j++)
#pragma unroll
            for (int k = 0; k < 4; k++) cc[i][j][k] = 0.f;

#define DN_LOAD(b, k0)                                               \
    do {                                                             \
        uint32_t o = sb + (b) * DN_BUF;                              \
        load_tile128(o,          ah,  INTER, (k0), nrows, tid);      \
        load_tile128(o + 10240,  al,  INTER, (k0), nrows, tid);      \
        load_tile128(o + 20480,  bh,  INTER, (k0), 128,   tid);      \
        load_tile128(o + 30720,  blo, INTER, (k0), 128,   tid);      \
        CP_COMMIT();                                                 \
    } while (0)

    DN_LOAD(0, 0);
    const int KT = INTER / 32;
    for (int kt = 0; kt < KT; kt++) {
        const bool more = (kt + 1 < KT);
        if (more) DN_LOAD((kt + 1) & 1, (kt + 1) * 32);
        if (more) CP_WAIT1(); else CP_WAIT0();
        __syncthreads();
        const uint32_t buf = sb + (kt & 1) * DN_BUF;
#pragma unroll
        for (int ks = 0; ks < 2; ks++) {
            const int k0 = ks * 16;
            uint32_t Ah0[4], Ah1[4], Al0[4], Al1[4];
            fragA(Ah0, buf,         wm * 32,      k0, lane);
            fragA(Ah1, buf,         wm * 32 + 16, k0, lane);
            fragA(Al0, buf + 10240, wm * 32,      k0, lane);
            fragA(Al1, buf + 10240, wm * 32 + 16, k0, lane);
#pragma unroll
            for (int p = 0; p < 4; p++) {
                const int nb = wn * 64 + p * 16;
                uint32_t Fbh[4], Fbl[4];
                fragB2(Fbh, buf + 20480, nb, k0, lane);
                fragB2(Fbl, buf + 30720, nb, k0, lane);
                const int q = p * 2;
                MMA(cc[0][q],   Ah0, Fbh);     MMA(cc[0][q],   Ah0, Fbl);     MMA(cc[0][q],   Al0, Fbh);
                MMA(cc[1][q],   Ah1, Fbh);     MMA(cc[1][q],   Ah1, Fbl);     MMA(cc[1][q],   Al1, Fbh);
                MMA(cc[0][q+1], Ah0, Fbh + 2); MMA(cc[0][q+1], Ah0, Fbl + 2); MMA(cc[0][q+1], Al0, Fbh + 2);
                MMA(cc[1][q+1], Ah1, Fbh + 2); MMA(cc[1][q+1], Ah1, Fbl + 2); MMA(cc[1][q+1], Al1, Fbh + 2);
            }
        }
        __syncthreads();
    }

    // epilogue: scale by probs, write fp32 out
#pragma unroll
    for (int mt = 0; mt < 2; mt++)
#pragma unroll
        for (int half = 0; half < 2; half++) {
            const int r = wm * 32 + mt * 16 + half * 8 + (lane >> 2);
            if (r < nrows) {
                const float p = probs[row0 + r];
                float* op = out + (size_t)(row0 + r) * HID + n0 + wn * 64;
#pragma unroll
                for (int nt = 0; nt < 8; nt++) {
                    const int col = nt * 8 + (lane & 3) * 2;
                    float2 v;
                    v.x = p * cc[mt][nt][half * 2];
                    v.y = p * cc[mt][nt][half * 2 + 1];
                    *(float2*)(op + col) = v;
                }
            }
        }
}

// ---------------------------------------------------------------------------
// Launch
// ---------------------------------------------------------------------------
extern "C" void kernel_launch(void* const* d_in, const int* in_sizes, int n_in,
                              void* d_out, int out_size) {
    const float* x     = (const float*)d_in[0];
    const float* probs = (const float*)d_in[1];
    const float* wg    = (const float*)d_in[2];
    const float* wu    = (const float*)d_in[3];
    const float* wd    = (const float*)d_in[4];
    const int*   tpe   = (const int*)d_in[5];
    float*       out   = (float*)d_out;

    cudaFuncSetAttribute(k_gateup, cudaFuncAttributeMaxDynamicSharedMemorySize, GU_SMEM);
    cudaFuncSetAttribute(k_down,   cudaFuncAttributeMaxDynamicSharedMemorySize, DN_SMEM);

    setup_tiles<<<1, 1>>>(tpe);
    convert_x<<<2048, 256>>>(x);

    dim3 tb(32, 8);
    transpose_cvt_gu<<<dim3(HID / 32, INTER / 32, 2 * NE), tb>>>(wg, wu);
    transpose_cvt_d<<<dim3(INTER / 32, HID / 32, NE), tb>>>(wd);

    k_gateup<<<dim3(INTER / 64, MAXGRIDY), 256, GU_SMEM>>>();
    k_down<<<dim3(HID / 128, MAXGRIDY), 256, DN_SMEM>>>(probs, out);
}